// round 15
// baseline (speedup 1.0000x reference)
#include <cuda_runtime.h>
#include <cuda_fp16.h>
#include <math.h>
#include <stdint.h>

#define BB 4
#define TT 1024
#define DD 2048
#define NH 16
#define NKV 4
#define HD 128
#define MROWS (BB*TT)    // 4096
#define NQKV 3072
#define SCALE 0.08838834764831845f   // 1/sqrt(128)

// Scratch (device globals; no runtime allocation)
__device__ __half   g_xh[MROWS * DD];          // x fp16 [4096][2048]
__device__ __half   g_Wqkvh[NQKV * DD];        // [Wq|Wk|Wv]^T fp16 [3072][2048]
__device__ __half   g_Woh[DD * DD];            // Wo^T fp16
__device__ __half   g_Qh[BB * NH * TT * HD];   // roped+scaled Q half [b][h][t][d]
__device__ __half   g_Kh[BB * NKV * TT * HD];  // roped K half [b][g][t][d]
__device__ __half   g_Vt[BB * NKV * HD * TT];  // V half TRANSPOSED [b][g][d][t]
__device__ __half   g_Yh[MROWS * DD];          // attention out half
__device__ float    g_cos[TT * 64];
__device__ float    g_sin[TT * 64];

#define MMA_F16(ACC, A0, A1, A2, A3, B0, B1)                                   \
    asm volatile(                                                              \
        "mma.sync.aligned.m16n8k16.row.col.f32.f16.f16.f32 "                   \
        "{%0,%1,%2,%3}, {%4,%5,%6,%7}, {%8,%9}, {%0,%1,%2,%3};"                \
        : "+f"((ACC)[0]), "+f"((ACC)[1]), "+f"((ACC)[2]), "+f"((ACC)[3])       \
        : "r"(A0), "r"(A1), "r"(A2), "r"(A3), "r"(B0), "r"(B1))

#define LDSM_X4(R, ADDR)                                                       \
    asm volatile(                                                              \
        "ldmatrix.sync.aligned.m8n8.x4.shared.b16 {%0,%1,%2,%3}, [%4];"        \
        : "=r"((R)[0]), "=r"((R)[1]), "=r"((R)[2]), "=r"((R)[3])               \
        : "r"(ADDR))

__device__ __forceinline__ void cp16(uint32_t dst, const void* src) {
    asm volatile("cp.async.cg.shared.global [%0], [%1], 16;" ::
                 "r"(dst), "l"(src));
}
#define CP_COMMIT() asm volatile("cp.async.commit_group;")
#define CP_WAIT(n)  asm volatile("cp.async.wait_group %0;" :: "n"(n) : "memory")

__device__ __forceinline__ uint32_t h2bits(float a, float b) {
    __half2 h = __floats2half2_rn(a, b);
    return *(uint32_t*)&h;
}

// ---------------------------------------------------------------------------
// FP16 GEMM: C = A[half, M x 2048 row-major] @ B^T[half, N x 2048 n-major].
// CTA 128x128, 256 threads = 8 warps (2M x 4N), warp tile 64x32.
// KT=32, 4 stages, LDSM fragment loads (row stride 80 B, conflict-free).
// 2 CTAs/SM -> 16 warps/SM.
// ---------------------------------------------------------------------------
#define HSTR 20                   // u32 per row
#define HAW  (128*HSTR)
#define HSTG (2*HAW)
#define GEMM_SMEM (4*HSTG*4)      // 81920 B

// Requires: a_off, b_off (lane-dependent LDSM byte offsets) defined by caller.
#define GEMM_MAINLOOP_H(Aptr, Bptr)                                            \
    auto LOAD = [&](int kt, int s) {                                           \
        uint32_t abase = smaddr + (uint32_t)(s * HSTG) * 4;                    \
        _Pragma("unroll")                                                      \
        for (int p = 0; p < 2; p++) {                                          \
            int id = tid + p * 256;                                            \
            int row = id >> 2, ch = id & 3;                                    \
            cp16(abase + (uint32_t)(row * 80 + ch * 16),                       \
                 (Aptr) + (size_t)(bm + row) * DD + kt * 32 + ch * 8);         \
        }                                                                      \
        uint32_t bbase = abase + HAW * 4;                                      \
        _Pragma("unroll")                                                      \
        for (int p = 0; p < 2; p++) {                                          \
            int id = tid + p * 256;                                            \
            int row = id >> 2, ch = id & 3;                                    \
            cp16(bbase + (uint32_t)(row * 80 + ch * 16),                       \
                 (Bptr) + (size_t)(bn + row) * DD + kt * 32 + ch * 8);         \
        }                                                                      \
        CP_COMMIT();                                                           \
    };                                                                         \
    LOAD(0, 0); LOAD(1, 1); LOAD(2, 2);                                        \
    for (int kt = 0; kt < 64; kt++) {                                          \
        CP_WAIT(2);                                                            \
        __syncthreads();                                                       \
        if (kt + 3 < 64) LOAD(kt + 3, (kt + 3) & 3);                           \
        else CP_COMMIT();                                                      \
        const uint32_t sbase = smaddr + (uint32_t)((kt & 3) * HSTG) * 4;       \
        const uint32_t aaddr = sbase + a_off;                                  \
        const uint32_t baddr = sbase + HAW * 4 + b_off;                        \
        _Pragma("unroll")                                                      \
        for (int kk = 0; kk < 2; kk++) {                                       \
            uint32_t af[4][4], bf[2][4];                                       \
            _Pragma("unroll")                                                  \
            for (int mi = 0; mi < 4; mi++)                                     \
                LDSM_X4(af[mi], aaddr + mi * 1280 + kk * 32);                  \
            _Pragma("unroll")                                                  \
            for (int np = 0; np < 2; np++)                                     \
                LDSM_X4(bf[np], baddr + np * 1280 + kk * 32);                  \
            _Pragma("unroll")                                                  \
            for (int mi = 0; mi < 4; mi++)                                     \
                _Pragma("unroll")                                              \
                for (int ni = 0; ni < 4; ni++)                                 \
                    MMA_F16(acc[mi][ni], af[mi][0], af[mi][1], af[mi][2],      \
                            af[mi][3], bf[ni >> 1][(ni & 1) * 2],              \
                            bf[ni >> 1][(ni & 1) * 2 + 1]);                    \
        }                                                                      \
    }

#define GEMM_LDSM_OFFS()                                                       \
    const uint32_t a_off = (uint32_t)((wm + (lane & 7) + ((lane >> 3) & 1) * 8)\
                                       * 80 + ((lane >> 4) & 1) * 16);         \
    const uint32_t b_off = (uint32_t)((wn + (lane & 7) + ((lane >> 4) & 1) * 8)\
                                       * 80 + ((lane >> 3) & 1) * 16)

// ---------------------------------------------------------------------------
// Fused QKV projection (fp16) + RoPE epilogue. Q is pre-scaled by 1/sqrt(d).
// ---------------------------------------------------------------------------
__global__ __launch_bounds__(256, 2) void gemm_qkv_h(
    const __half* __restrict__ A, const __half* __restrict__ B,
    __half* __restrict__ Qh, __half* __restrict__ Kh,
    __half* __restrict__ Vt)
{
    extern __shared__ uint32_t smg[];
    const uint32_t smaddr = (uint32_t)__cvta_generic_to_shared(smg);

    const int tid  = threadIdx.x;
    const int bm   = blockIdx.y * 128;
    const int bn   = blockIdx.x * 128;
    const int warp = tid >> 5, lane = tid & 31;
    const int wm   = (warp & 1) * 64;
    const int wn   = (warp >> 1) * 32;
    const int gID  = lane >> 2, tig = lane & 3;
    GEMM_LDSM_OFFS();

    float acc[4][4][4];
#pragma unroll
    for (int i = 0; i < 4; i++)
#pragma unroll
        for (int j = 0; j < 4; j++)
#pragma unroll
            for (int l = 0; l < 4; l++) acc[i][j][l] = 0.f;

    GEMM_MAINLOOP_H(A, B)

    __syncthreads();
    float* Cs = (float*)smg;       // 128*132 u32 = 67584 B < 81920 B
#pragma unroll
    for (int mi = 0; mi < 4; mi++) {
        const int r0 = wm + mi * 16 + gID;
#pragma unroll
        for (int ni = 0; ni < 4; ni++) {
            const int c = wn + ni * 8 + tig * 2;
            Cs[r0 * 132 + c]     = acc[mi][ni][0];
            Cs[r0 * 132 + c + 1] = acc[mi][ni][1];
            Cs[(r0 + 8) * 132 + c]     = acc[mi][ni][2];
            Cs[(r0 + 8) * 132 + c + 1] = acc[mi][ni][3];
        }
    }
    __syncthreads();

    const int bb = bm >> 10;
    if (bn < 2560) {
        __half* dst;
        int head, hs;
        float sc;
        if (bn < 2048) { dst = Qh; head = bn >> 7;          hs = NH;  sc = SCALE; }
        else           { dst = Kh; head = (bn - 2048) >> 7; hs = NKV; sc = 1.f;   }
#pragma unroll 4
        for (int p = 0; p < 16; p++) {
            int idx = tid + p * 256;
            int r = idx >> 5;
            int d2 = (idx & 31) << 1;
            int t = (bm + r) & (TT - 1);
            float lo0 = Cs[r * 132 + d2] * sc;
            float lo1 = Cs[r * 132 + d2 + 1] * sc;
            float hi0 = Cs[r * 132 + d2 + 64] * sc;
            float hi1 = Cs[r * 132 + d2 + 65] * sc;
            float2 cc = *(const float2*)(g_cos + t * 64 + d2);
            float2 ss = *(const float2*)(g_sin + t * 64 + d2);
            __half* o = dst + ((size_t)(bb * hs + head) * TT + t) * HD;
            *(__half2*)(o + d2) =
                __floats2half2_rn(lo0 * cc.x - hi0 * ss.x,
                                  lo1 * cc.y - hi1 * ss.y);
            *(__half2*)(o + d2 + 64) =
                __floats2half2_rn(hi0 * cc.x + lo0 * ss.x,
                                  hi1 * cc.y + lo1 * ss.y);
        }
    } else {
        const int head = (bn - 2560) >> 7;
        const int d  = tid & 127;
        const int th = (tid >> 7) * 64;    // 0 or 64
        const int t0 = bm & (TT - 1);
        __half* o = Vt + ((size_t)(bb * NKV + head) * HD + d) * TT + t0;
#pragma unroll 8
        for (int tq = th; tq < th + 64; tq += 2) {
            float v0 = Cs[tq * 132 + d];
            float v1 = Cs[(tq + 1) * 132 + d];
            *(__half2*)(o + tq) = __floats2half2_rn(v0, v1);
        }
    }
}

// ---------------------------------------------------------------------------
// Wo projection (fp16): out fp32 = Yh @ Woh^T-tile
// ---------------------------------------------------------------------------
__global__ __launch_bounds__(256, 2) void gemm_wo_h(
    const __half* __restrict__ A, const __half* __restrict__ B,
    float* __restrict__ C)
{
    extern __shared__ uint32_t smg[];
    const uint32_t smaddr = (uint32_t)__cvta_generic_to_shared(smg);

    const int tid  = threadIdx.x;
    const int bm   = blockIdx.y * 128;
    const int bn   = blockIdx.x * 128;
    const int warp = tid >> 5, lane = tid & 31;
    const int wm   = (warp & 1) * 64;
    const int wn   = (warp >> 1) * 32;
    const int gID  = lane >> 2, tig = lane & 3;
    GEMM_LDSM_OFFS();

    float acc[4][4][4];
#pragma unroll
    for (int i = 0; i < 4; i++)
#pragma unroll
        for (int j = 0; j < 4; j++)
#pragma unroll
            for (int l = 0; l < 4; l++) acc[i][j][l] = 0.f;

    GEMM_MAINLOOP_H(A, B)

#pragma unroll
    for (int mi = 0; mi < 4; mi++) {
        const int r0 = bm + wm + mi * 16 + gID;
#pragma unroll
        for (int ni = 0; ni < 4; ni++) {
            const int c = bn + wn + ni * 8 + tig * 2;
            *(float2*)&C[(size_t)r0 * DD + c] =
                make_float2(acc[mi][ni][0], acc[mi][ni][1]);
            *(float2*)&C[(size_t)(r0 + 8) * DD + c] =
                make_float2(acc[mi][ni][2], acc[mi][ni][3]);
        }
    }
}

// ---------------------------------------------------------------------------
// Prep kernels
// ---------------------------------------------------------------------------
__global__ void cvt_h(const float* __restrict__ in, __half* __restrict__ out)
{
    int i = (blockIdx.x * 256 + threadIdx.x) * 4;
    float4 v = *(const float4*)(in + i);
    *(__half2*)(out + i)     = __floats2half2_rn(v.x, v.y);
    *(__half2*)(out + i + 2) = __floats2half2_rn(v.z, v.w);
}

__global__ void tr_cvt_all(const float* __restrict__ Wq,
                           const float* __restrict__ Wk,
                           const float* __restrict__ Wv,
                           const float* __restrict__ Wo,
                           __half* __restrict__ Wqkvh,
                           __half* __restrict__ Woh)
{
    __shared__ float tile[32][33];
    const int z = blockIdx.z;
    const float* src;
    __half* dst;
    int C, row_off;
    if      (z == 0) { src = Wq; dst = Wqkvh; C = 2048; row_off = 0;    }
    else if (z == 1) { src = Wk; dst = Wqkvh; C = 512;  row_off = 2048; }
    else if (z == 2) { src = Wv; dst = Wqkvh; C = 512;  row_off = 2560; }
    else             { src = Wo; dst = Woh;   C = 2048; row_off = 0;    }

    int bx = blockIdx.x * 32;
    if (bx >= C) return;
    int by = blockIdx.y * 32;
    int x = threadIdx.x, y = threadIdx.y;   // 32 x 8
#pragma unroll
    for (int j = 0; j < 32; j += 8)
        tile[y + j][x] = src[(size_t)(by + y + j) * C + bx + x];
    __syncthreads();
#pragma unroll
    for (int j = 0; j < 32; j += 8)
        dst[(size_t)(row_off + bx + y + j) * 2048 + by + x] =
            __float2half(tile[x][y + j]);
}

__global__ void rope_table_kernel()
{
    int t = blockIdx.x;
    int i = threadIdx.x;
    float inv = powf(10000.0f, -(float)i / 64.0f);
    float ang = (float)t * inv;
    g_cos[t * 64 + i] = cosf(ang);
    g_sin[t * 64 + i] = sinf(ang);
}

// ---------------------------------------------------------------------------
// FP16 flash attention, causal, GQA. BQ=128, BS=128. (unchanged from R13)
// ---------------------------------------------------------------------------
#define QSTR 68
#define KSTR 68
#define VSTR 68
#define PSTR 68
#define ATTN_SMEM (43520 * 4)

__global__ __launch_bounds__(256, 1) void attn_h(
    const __half* __restrict__ Qh, const __half* __restrict__ Kh,
    const __half* __restrict__ Vt, __half* __restrict__ Y)
{
    extern __shared__ uint32_t sma[];
    uint32_t* Qs  = sma;
    uint32_t* Ks  = Qs + 128 * QSTR;
    uint32_t* Vsb = Ks + 128 * KSTR;
    uint32_t* Ps  = Vsb + 2 * 128 * VSTR;
    const uint32_t smaddr = (uint32_t)__cvta_generic_to_shared(sma);
    const uint32_t Qs_a = smaddr;
    const uint32_t Ks_a = Qs_a + 128 * QSTR * 4;
    const uint32_t Vs_a = Ks_a + 128 * KSTR * 4;

    const int tid  = threadIdx.x;
    const int warp = tid >> 5, lane = tid & 31;
    const int gID  = lane >> 2, tig = lane & 3;
    const int qt   = (gridDim.x - 1) - blockIdx.x;
    const int hh   = blockIdx.y;
    const int b    = blockIdx.z;
    const int gkv  = hh >> 2;
    const int q0   = qt * 128;
    const int wm   = warp * 16;
    const int row0 = q0 + wm + gID;

    const __half* Qbase = Qh + ((size_t)(b * NH + hh) * TT + q0) * HD;
    const __half* Kbase = Kh + (size_t)(b * NKV + gkv) * TT * HD;
    const __half* Vbase = Vt + (size_t)(b * NKV + gkv) * HD * TT;

    auto LOADQ = [&]() {
#pragma unroll
        for (int p = 0; p < 8; p++) {
            int id = tid + p * 256;
            int q = id >> 4, ch = id & 15;
            cp16(Qs_a + (uint32_t)(q * QSTR + ch * 4) * 4,
                 Qbase + q * HD + ch * 8);
        }
    };
    auto LOADK = [&](int st) {
        const __half* src = Kbase + (size_t)st * 128 * HD;
#pragma unroll
        for (int p = 0; p < 8; p++) {
            int id = tid + p * 256;
            int s = id >> 4, ch = id & 15;
            cp16(Ks_a + (uint32_t)(s * KSTR + ch * 4) * 4,
                 src + s * HD + ch * 8);
        }
    };
    auto LOADV = [&](int st) {
        const __half* src = Vbase + st * 128;
        uint32_t dbase = Vs_a + (uint32_t)((st & 1) * 128 * VSTR) * 4;
#pragma unroll
        for (int p = 0; p < 8; p++) {
            int id = tid + p * 256;
            int d = id >> 4, ch = id & 15;
            cp16(dbase + (uint32_t)(d * VSTR + ch * 4) * 4,
                 src + (size_t)d * TT + ch * 8);
        }
    };

    const int ntiles = qt + 1;

    LOADQ(); LOADK(0); LOADV(0); CP_COMMIT();
    if (ntiles > 1) LOADV(1);
    CP_COMMIT();

    float m0 = -1e30f, m1 = -1e30f, l0 = 0.f, l1 = 0.f;
    float oacc[16][4];
#pragma unroll
    for (int i = 0; i < 16; i++)
#pragma unroll
        for (int j = 0; j < 4; j++) oacc[i][j] = 0.f;

    for (int st = 0; st < ntiles; st++) {
        const int s0 = st * 128;

        CP_WAIT(1);
        __syncthreads();

        float sacc[16][4];
#pragma unroll
        for (int i = 0; i < 16; i++)
#pragma unroll
            for (int j = 0; j < 4; j++) sacc[i][j] = 0.f;

        const uint32_t* qrow = Qs + (wm + gID) * QSTR;
#pragma unroll
        for (int kk = 0; kk < 8; kk++) {
            const int k0 = kk * 8;
            uint32_t a0 = qrow[k0 + tig];
            uint32_t a1 = qrow[8 * QSTR + k0 + tig];
            uint32_t a2 = qrow[k0 + tig + 4];
            uint32_t a3 = qrow[8 * QSTR + k0 + tig + 4];
#pragma unroll
            for (int ni = 0; ni < 16; ni++) {
                const uint32_t* kp = Ks + (gID + ni * 8) * KSTR + k0;
                MMA_F16(sacc[ni], a0, a1, a2, a3, kp[tig], kp[tig + 4]);
            }
        }
        __syncthreads();

        if (st + 1 < ntiles) LOADK(st + 1);
        CP_COMMIT();

        const int lim0 = row0 - s0;
        const int lim1 = lim0 + 8;
        const bool diag = (st == qt);
        float mx0 = -1e30f, mx1 = -1e30f;
#pragma unroll
        for (int ni = 0; ni < 16; ni++) {
#pragma unroll
            for (int c = 0; c < 2; c++) {
                int j = ni * 8 + tig * 2 + c;
                float v0 = sacc[ni][c];
                float v1 = sacc[ni][2 + c];
                if (diag) {
                    if (j > lim0) v0 = -1e30f;
                    if (j > lim1) v1 = -1e30f;
                }
                sacc[ni][c]     = v0;
                sacc[ni][2 + c] = v1;
                mx0 = fmaxf(mx0, v0);
                mx1 = fmaxf(mx1, v1);
            }
        }
        mx0 = fmaxf(mx0, __shfl_xor_sync(0xffffffffu, mx0, 1));
        mx0 = fmaxf(mx0, __shfl_xor_sync(0xffffffffu, mx0, 2));
        mx1 = fmaxf(mx1, __shfl_xor_sync(0xffffffffu, mx1, 1));
        mx1 = fmaxf(mx1, __shfl_xor_sync(0xffffffffu, mx1, 2));
        float mn0 = fmaxf(m0, mx0), mn1 = fmaxf(m1, mx1);
        float cr0 = __expf(m0 - mn0), cr1 = __expf(m1 - mn1);
        float sum0 = 0.f, sum1 = 0.f;
#pragma unroll
        for (int ni = 0; ni < 16; ni++) {
#pragma unroll
            for (int c = 0; c < 2; c++) {
                float p0 = __expf(sacc[ni][c] - mn0);
                float p1 = __expf(sacc[ni][2 + c] - mn1);
                sacc[ni][c]     = p0;
                sacc[ni][2 + c] = p1;
                sum0 += p0;
                sum1 += p1;
            }
        }
        sum0 += __shfl_xor_sync(0xffffffffu, sum0, 1);
        sum0 += __shfl_xor_sync(0xffffffffu, sum0, 2);
        sum1 += __shfl_xor_sync(0xffffffffu, sum1, 1);
        sum1 += __shfl_xor_sync(0xffffffffu, sum1, 2);
        l0 = l0 * cr0 + sum0;
        l1 = l1 * cr1 + sum1;
        m0 = mn0; m1 = mn1;

#pragma unroll
        for (int ni = 0; ni < 16; ni++) {
            oacc[ni][0] *= cr0; oacc[ni][1] *= cr0;
            oacc[ni][2] *= cr1; oacc[ni][3] *= cr1;
        }

        uint32_t* pr0 = Ps + (wm + gID) * PSTR;
        uint32_t* pr1 = pr0 + 8 * PSTR;
#pragma unroll
        for (int ni = 0; ni < 16; ni++) {
            pr0[ni * 4 + tig] = h2bits(sacc[ni][0], sacc[ni][1]);
            pr1[ni * 4 + tig] = h2bits(sacc[ni][2], sacc[ni][3]);
        }
        __syncwarp();

        const uint32_t* vbuf = Vsb + (st & 1) * 128 * VSTR;
        const uint32_t* prow = Ps + (wm + gID) * PSTR;
#pragma unroll
        for (int kk = 0; kk < 8; kk++) {
            const int k0 = kk * 8;
            uint32_t a0 = prow[k0 + tig];
            uint32_t a1 = prow[8 * PSTR + k0 + tig];
            uint32_t a2 = prow[k0 + tig + 4];
            uint32_t a3 = prow[8 * PSTR + k0 + tig + 4];
#pragma unroll
            for (int ni = 0; ni < 16; ni++) {
                const uint32_t* vp = vbuf + (gID + ni * 8) * VSTR + k0;
                MMA_F16(oacc[ni], a0, a1, a2, a3, vp[tig], vp[tig + 4]);
            }
        }
        __syncthreads();

        if (st + 2 < ntiles) LOADV(st + 2);
        CP_COMMIT();
    }

    float li0 = 1.f / l0, li1 = 1.f / l1;
    __half* y0 = Y + (size_t)(b * TT + row0) * DD + hh * HD;
    __half* y1 = y0 + (size_t)8 * DD;
#pragma unroll
    for (int ni = 0; ni < 16; ni++) {
        int c = ni * 8 + tig * 2;
        *(__half2*)(y0 + c) = __floats2half2_rn(oacc[ni][0] * li0,
                                                oacc[ni][1] * li0);
        *(__half2*)(y1 + c) = __floats2half2_rn(oacc[ni][2] * li1,
                                                oacc[ni][3] * li1);
    }
}

// ---------------------------------------------------------------------------
extern "C" void kernel_launch(void* const* d_in, const int* in_sizes, int n_in,
                              void* d_out, int out_size)
{
    const float* x  = (const float*)d_in[0];
    const float* Wq = (const float*)d_in[1];
    const float* Wk = (const float*)d_in[2];
    const float* Wv = (const float*)d_in[3];
    const float* Wo = (const float*)d_in[4];
    float* out = (float*)d_out;

    __half *xh, *Wqkvh, *Woh, *Qh, *Kh, *Vt, *Yh;
    cudaGetSymbolAddress((void**)&xh,    g_xh);
    cudaGetSymbolAddress((void**)&Wqkvh, g_Wqkvh);
    cudaGetSymbolAddress((void**)&Woh,   g_Woh);
    cudaGetSymbolAddress((void**)&Qh,    g_Qh);
    cudaGetSymbolAddress((void**)&Kh,    g_Kh);
    cudaGetSymbolAddress((void**)&Vt,    g_Vt);
    cudaGetSymbolAddress((void**)&Yh,    g_Yh);

    static bool attr_set = false;
    if (!attr_set) {
        cudaFuncSetAttribute(gemm_qkv_h,
                             cudaFuncAttributeMaxDynamicSharedMemorySize,
                             GEMM_SMEM);
        cudaFuncSetAttribute(gemm_wo_h,
                             cudaFuncAttributeMaxDynamicSharedMemorySize,
                             GEMM_SMEM);
        cudaFuncSetAttribute(attn_h,
                             cudaFuncAttributeMaxDynamicSharedMemorySize,
                             ATTN_SMEM);
        attr_set = true;
    }

    rope_table_kernel<<<TT, 64>>>();
    cvt_h<<<(MROWS * DD) / 1024, 256>>>(x, xh);
    tr_cvt_all<<<dim3(64, 64, 4), dim3(32, 8)>>>(Wq, Wk, Wv, Wo, Wqkvh, Woh);

    // Fused QKV projection + RoPE (+Q scaling) -> half Qh/Kh, transposed Vt
    gemm_qkv_h<<<dim3(NQKV / 128, MROWS / 128), 256, GEMM_SMEM>>>(
        xh, Wqkvh, Qh, Kh, Vt);

    // FP16 flash attention (BQ=BS=128) -> Yh
    attn_h<<<dim3(TT / 128, NH, BB), 256, ATTN_SMEM>>>(Qh, Kh, Vt, Yh);

    // Output projection
    gemm_wo_h<<<dim3(DD / 128, MROWS / 128), 256, GEMM_SMEM>>>(Yh, Woh, out);
}

// round 16
// speedup vs baseline: 1.0950x; 1.0950x over previous
#include <cuda_runtime.h>
#include <cuda_fp16.h>
#include <math.h>
#include <stdint.h>

#define BB 4
#define TT 1024
#define DD 2048
#define NH 16
#define NKV 4
#define HD 128
#define MROWS (BB*TT)    // 4096
#define NQKV 3072
#define SCALE 0.08838834764831845f   // 1/sqrt(128)

// Scratch (device globals; no runtime allocation)
__device__ __half   g_xh[MROWS * DD];          // x fp16 [4096][2048]
__device__ __half   g_Wqkvh[NQKV * DD];        // [Wq|Wk|Wv]^T fp16 [3072][2048]
__device__ __half   g_Woh[DD * DD];            // Wo^T fp16
__device__ __half   g_Qh[BB * NH * TT * HD];   // roped+scaled Q half [b][h][t][d]
__device__ __half   g_Kh[BB * NKV * TT * HD];  // roped K half [b][g][t][d]
__device__ __half   g_Vt[BB * NKV * HD * TT];  // V half TRANSPOSED [b][g][d][t]
__device__ __half   g_Yh[MROWS * DD];          // attention out half
__device__ float    g_cos[TT * 64];
__device__ float    g_sin[TT * 64];

#define MMA_F16(ACC, A0, A1, A2, A3, B0, B1)                                   \
    asm volatile(                                                              \
        "mma.sync.aligned.m16n8k16.row.col.f32.f16.f16.f32 "                   \
        "{%0,%1,%2,%3}, {%4,%5,%6,%7}, {%8,%9}, {%0,%1,%2,%3};"                \
        : "+f"((ACC)[0]), "+f"((ACC)[1]), "+f"((ACC)[2]), "+f"((ACC)[3])       \
        : "r"(A0), "r"(A1), "r"(A2), "r"(A3), "r"(B0), "r"(B1))

#define LDSM_X4(R, ADDR)                                                       \
    asm volatile(                                                              \
        "ldmatrix.sync.aligned.m8n8.x4.shared.b16 {%0,%1,%2,%3}, [%4];"        \
        : "=r"((R)[0]), "=r"((R)[1]), "=r"((R)[2]), "=r"((R)[3])               \
        : "r"(ADDR))

__device__ __forceinline__ void cp16(uint32_t dst, const void* src) {
    asm volatile("cp.async.cg.shared.global [%0], [%1], 16;" ::
                 "r"(dst), "l"(src));
}
#define CP_COMMIT() asm volatile("cp.async.commit_group;")
#define CP_WAIT(n)  asm volatile("cp.async.wait_group %0;" :: "n"(n) : "memory")

__device__ __forceinline__ uint32_t h2bits(float a, float b) {
    __half2 h = __floats2half2_rn(a, b);
    return *(uint32_t*)&h;
}

// ---------------------------------------------------------------------------
// FP16 GEMM: C = A[half, M x 2048 row-major] @ B^T[half, N x 2048 n-major].
// CTA 128x128, 128 threads (4 warps, 2Mx2N, warp 64x64), KT=32, 4 stages.
// LDSM fragment loads (row stride 80 B), all 16 LDSM issued before the 64
// MMAs of the k-tile (explicit register double-buffering across kk).
// ---------------------------------------------------------------------------
#define HSTR 20                   // u32 per row
#define HAW  (128*HSTR)
#define HSTG (2*HAW)
#define GEMM_SMEM (4*HSTG*4)      // 81920 B

// Requires: a_off, b_off (lane-dependent LDSM byte offsets) defined by caller.
#define GEMM_MAINLOOP_H(Aptr, Bptr)                                            \
    auto LOAD = [&](int kt, int s) {                                           \
        uint32_t abase = smaddr + (uint32_t)(s * HSTG) * 4;                    \
        _Pragma("unroll")                                                      \
        for (int p = 0; p < 4; p++) {                                          \
            int id = tid + p * 128;                                            \
            int row = id >> 2, ch = id & 3;                                    \
            cp16(abase + (uint32_t)(row * 80 + ch * 16),                       \
                 (Aptr) + (size_t)(bm + row) * DD + kt * 32 + ch * 8);         \
        }                                                                      \
        uint32_t bbase = abase + HAW * 4;                                      \
        _Pragma("unroll")                                                      \
        for (int p = 0; p < 4; p++) {                                          \
            int id = tid + p * 128;                                            \
            int row = id >> 2, ch = id & 3;                                    \
            cp16(bbase + (uint32_t)(row * 80 + ch * 16),                       \
                 (Bptr) + (size_t)(bn + row) * DD + kt * 32 + ch * 8);         \
        }                                                                      \
        CP_COMMIT();                                                           \
    };                                                                         \
    LOAD(0, 0); LOAD(1, 1); LOAD(2, 2);                                        \
    for (int kt = 0; kt < 64; kt++) {                                          \
        CP_WAIT(2);                                                            \
        __syncthreads();                                                       \
        if (kt + 3 < 64) LOAD(kt + 3, (kt + 3) & 3);                           \
        else CP_COMMIT();                                                      \
        const uint32_t sbase = smaddr + (uint32_t)((kt & 3) * HSTG) * 4;       \
        const uint32_t aaddr = sbase + a_off;                                  \
        const uint32_t baddr = sbase + HAW * 4 + b_off;                        \
        uint32_t af[2][4][4], bf[2][4][4];                                     \
        _Pragma("unroll")                                                      \
        for (int kk = 0; kk < 2; kk++) {                                       \
            _Pragma("unroll")                                                  \
            for (int mi = 0; mi < 4; mi++)                                     \
                LDSM_X4(af[kk][mi], aaddr + mi * 1280 + kk * 32);              \
            _Pragma("unroll")                                                  \
            for (int np = 0; np < 4; np++)                                     \
                LDSM_X4(bf[kk][np], baddr + np * 1280 + kk * 32);              \
        }                                                                      \
        _Pragma("unroll")                                                      \
        for (int kk = 0; kk < 2; kk++)                                         \
            _Pragma("unroll")                                                  \
            for (int mi = 0; mi < 4; mi++)                                     \
                _Pragma("unroll")                                              \
                for (int ni = 0; ni < 8; ni++)                                 \
                    MMA_F16(acc[mi][ni], af[kk][mi][0], af[kk][mi][1],         \
                            af[kk][mi][2], af[kk][mi][3],                      \
                            bf[kk][ni >> 1][(ni & 1) * 2],                     \
                            bf[kk][ni >> 1][(ni & 1) * 2 + 1]);                \
    }

#define GEMM_LDSM_OFFS()                                                       \
    const uint32_t a_off = (uint32_t)((wm + (lane & 7) + ((lane >> 3) & 1) * 8)\
                                       * 80 + ((lane >> 4) & 1) * 16);         \
    const uint32_t b_off = (uint32_t)((wn + (lane & 7) + ((lane >> 4) & 1) * 8)\
                                       * 80 + ((lane >> 3) & 1) * 16)

// ---------------------------------------------------------------------------
// Fused QKV projection (fp16) + RoPE epilogue. Q is pre-scaled by 1/sqrt(d).
// ---------------------------------------------------------------------------
__global__ __launch_bounds__(128, 2) void gemm_qkv_h(
    const __half* __restrict__ A, const __half* __restrict__ B,
    __half* __restrict__ Qh, __half* __restrict__ Kh,
    __half* __restrict__ Vt)
{
    extern __shared__ uint32_t smg[];
    const uint32_t smaddr = (uint32_t)__cvta_generic_to_shared(smg);

    const int tid  = threadIdx.x;
    const int bm   = blockIdx.y * 128;
    const int bn   = blockIdx.x * 128;
    const int warp = tid >> 5, lane = tid & 31;
    const int wm   = (warp & 1) * 64;
    const int wn   = (warp >> 1) * 64;
    const int gID  = lane >> 2, tig = lane & 3;
    GEMM_LDSM_OFFS();

    float acc[4][8][4];
#pragma unroll
    for (int i = 0; i < 4; i++)
#pragma unroll
        for (int j = 0; j < 8; j++)
#pragma unroll
            for (int l = 0; l < 4; l++) acc[i][j][l] = 0.f;

    GEMM_MAINLOOP_H(A, B)

    __syncthreads();
    float* Cs = (float*)smg;       // 128*132 u32 = 67584 B < 81920 B
#pragma unroll
    for (int mi = 0; mi < 4; mi++) {
        const int r0 = wm + mi * 16 + gID;
#pragma unroll
        for (int ni = 0; ni < 8; ni++) {
            const int c = wn + ni * 8 + tig * 2;
            Cs[r0 * 132 + c]     = acc[mi][ni][0];
            Cs[r0 * 132 + c + 1] = acc[mi][ni][1];
            Cs[(r0 + 8) * 132 + c]     = acc[mi][ni][2];
            Cs[(r0 + 8) * 132 + c + 1] = acc[mi][ni][3];
        }
    }
    __syncthreads();

    const int bb = bm >> 10;
    if (bn < 2560) {
        __half* dst;
        int head, hs;
        float sc;
        if (bn < 2048) { dst = Qh; head = bn >> 7;          hs = NH;  sc = SCALE; }
        else           { dst = Kh; head = (bn - 2048) >> 7; hs = NKV; sc = 1.f;   }
#pragma unroll 4
        for (int p = 0; p < 32; p++) {
            int idx = tid + p * 128;
            int r = idx >> 5;
            int d2 = (idx & 31) << 1;
            int t = (bm + r) & (TT - 1);
            float lo0 = Cs[r * 132 + d2] * sc;
            float lo1 = Cs[r * 132 + d2 + 1] * sc;
            float hi0 = Cs[r * 132 + d2 + 64] * sc;
            float hi1 = Cs[r * 132 + d2 + 65] * sc;
            float2 cc = *(const float2*)(g_cos + t * 64 + d2);
            float2 ss = *(const float2*)(g_sin + t * 64 + d2);
            __half* o = dst + ((size_t)(bb * hs + head) * TT + t) * HD;
            *(__half2*)(o + d2) =
                __floats2half2_rn(lo0 * cc.x - hi0 * ss.x,
                                  lo1 * cc.y - hi1 * ss.y);
            *(__half2*)(o + d2 + 64) =
                __floats2half2_rn(hi0 * cc.x + lo0 * ss.x,
                                  hi1 * cc.y + lo1 * ss.y);
        }
    } else {
        const int head = (bn - 2560) >> 7;
        const int d = tid;
        const int t0 = bm & (TT - 1);
        __half* o = Vt + ((size_t)(bb * NKV + head) * HD + d) * TT + t0;
#pragma unroll 8
        for (int tq = 0; tq < 128; tq += 2) {
            float v0 = Cs[tq * 132 + d];
            float v1 = Cs[(tq + 1) * 132 + d];
            *(__half2*)(o + tq) = __floats2half2_rn(v0, v1);
        }
    }
}

// ---------------------------------------------------------------------------
// Wo projection (fp16): out fp32 = Yh @ Woh^T-tile
// ---------------------------------------------------------------------------
__global__ __launch_bounds__(128, 2) void gemm_wo_h(
    const __half* __restrict__ A, const __half* __restrict__ B,
    float* __restrict__ C)
{
    extern __shared__ uint32_t smg[];
    const uint32_t smaddr = (uint32_t)__cvta_generic_to_shared(smg);

    const int tid  = threadIdx.x;
    const int bm   = blockIdx.y * 128;
    const int bn   = blockIdx.x * 128;
    const int warp = tid >> 5, lane = tid & 31;
    const int wm   = (warp & 1) * 64;
    const int wn   = (warp >> 1) * 64;
    const int gID  = lane >> 2, tig = lane & 3;
    GEMM_LDSM_OFFS();

    float acc[4][8][4];
#pragma unroll
    for (int i = 0; i < 4; i++)
#pragma unroll
        for (int j = 0; j < 8; j++)
#pragma unroll
            for (int l = 0; l < 4; l++) acc[i][j][l] = 0.f;

    GEMM_MAINLOOP_H(A, B)

#pragma unroll
    for (int mi = 0; mi < 4; mi++) {
        const int r0 = bm + wm + mi * 16 + gID;
#pragma unroll
        for (int ni = 0; ni < 8; ni++) {
            const int c = bn + wn + ni * 8 + tig * 2;
            *(float2*)&C[(size_t)r0 * DD + c] =
                make_float2(acc[mi][ni][0], acc[mi][ni][1]);
            *(float2*)&C[(size_t)(r0 + 8) * DD + c] =
                make_float2(acc[mi][ni][2], acc[mi][ni][3]);
        }
    }
}

// ---------------------------------------------------------------------------
// Prep kernels
// ---------------------------------------------------------------------------
__global__ void cvt_h(const float* __restrict__ in, __half* __restrict__ out)
{
    int i = (blockIdx.x * 256 + threadIdx.x) * 4;
    float4 v = *(const float4*)(in + i);
    *(__half2*)(out + i)     = __floats2half2_rn(v.x, v.y);
    *(__half2*)(out + i + 2) = __floats2half2_rn(v.z, v.w);
}

__global__ void tr_cvt_all(const float* __restrict__ Wq,
                           const float* __restrict__ Wk,
                           const float* __restrict__ Wv,
                           const float* __restrict__ Wo,
                           __half* __restrict__ Wqkvh,
                           __half* __restrict__ Woh)
{
    __shared__ float tile[32][33];
    const int z = blockIdx.z;
    const float* src;
    __half* dst;
    int C, row_off;
    if      (z == 0) { src = Wq; dst = Wqkvh; C = 2048; row_off = 0;    }
    else if (z == 1) { src = Wk; dst = Wqkvh; C = 512;  row_off = 2048; }
    else if (z == 2) { src = Wv; dst = Wqkvh; C = 512;  row_off = 2560; }
    else             { src = Wo; dst = Woh;   C = 2048; row_off = 0;    }

    int bx = blockIdx.x * 32;
    if (bx >= C) return;
    int by = blockIdx.y * 32;
    int x = threadIdx.x, y = threadIdx.y;   // 32 x 8
#pragma unroll
    for (int j = 0; j < 32; j += 8)
        tile[y + j][x] = src[(size_t)(by + y + j) * C + bx + x];
    __syncthreads();
#pragma unroll
    for (int j = 0; j < 32; j += 8)
        dst[(size_t)(row_off + bx + y + j) * 2048 + by + x] =
            __float2half(tile[x][y + j]);
}

__global__ void rope_table_kernel()
{
    int t = blockIdx.x;
    int i = threadIdx.x;
    float inv = powf(10000.0f, -(float)i / 64.0f);
    float ang = (float)t * inv;
    g_cos[t * 64 + i] = cosf(ang);
    g_sin[t * 64 + i] = sinf(ang);
}

// ---------------------------------------------------------------------------
// FP16 flash attention, causal, GQA. BQ=128, BS=128. (unchanged from R13)
// ---------------------------------------------------------------------------
#define QSTR 68
#define KSTR 68
#define VSTR 68
#define PSTR 68
#define ATTN_SMEM (43520 * 4)

__global__ __launch_bounds__(256, 1) void attn_h(
    const __half* __restrict__ Qh, const __half* __restrict__ Kh,
    const __half* __restrict__ Vt, __half* __restrict__ Y)
{
    extern __shared__ uint32_t sma[];
    uint32_t* Qs  = sma;
    uint32_t* Ks  = Qs + 128 * QSTR;
    uint32_t* Vsb = Ks + 128 * KSTR;
    uint32_t* Ps  = Vsb + 2 * 128 * VSTR;
    const uint32_t smaddr = (uint32_t)__cvta_generic_to_shared(sma);
    const uint32_t Qs_a = smaddr;
    const uint32_t Ks_a = Qs_a + 128 * QSTR * 4;
    const uint32_t Vs_a = Ks_a + 128 * KSTR * 4;

    const int tid  = threadIdx.x;
    const int warp = tid >> 5, lane = tid & 31;
    const int gID  = lane >> 2, tig = lane & 3;
    const int qt   = (gridDim.x - 1) - blockIdx.x;
    const int hh   = blockIdx.y;
    const int b    = blockIdx.z;
    const int gkv  = hh >> 2;
    const int q0   = qt * 128;
    const int wm   = warp * 16;
    const int row0 = q0 + wm + gID;

    const __half* Qbase = Qh + ((size_t)(b * NH + hh) * TT + q0) * HD;
    const __half* Kbase = Kh + (size_t)(b * NKV + gkv) * TT * HD;
    const __half* Vbase = Vt + (size_t)(b * NKV + gkv) * HD * TT;

    auto LOADQ = [&]() {
#pragma unroll
        for (int p = 0; p < 8; p++) {
            int id = tid + p * 256;
            int q = id >> 4, ch = id & 15;
            cp16(Qs_a + (uint32_t)(q * QSTR + ch * 4) * 4,
                 Qbase + q * HD + ch * 8);
        }
    };
    auto LOADK = [&](int st) {
        const __half* src = Kbase + (size_t)st * 128 * HD;
#pragma unroll
        for (int p = 0; p < 8; p++) {
            int id = tid + p * 256;
            int s = id >> 4, ch = id & 15;
            cp16(Ks_a + (uint32_t)(s * KSTR + ch * 4) * 4,
                 src + s * HD + ch * 8);
        }
    };
    auto LOADV = [&](int st) {
        const __half* src = Vbase + st * 128;
        uint32_t dbase = Vs_a + (uint32_t)((st & 1) * 128 * VSTR) * 4;
#pragma unroll
        for (int p = 0; p < 8; p++) {
            int id = tid + p * 256;
            int d = id >> 4, ch = id & 15;
            cp16(dbase + (uint32_t)(d * VSTR + ch * 4) * 4,
                 src + (size_t)d * TT + ch * 8);
        }
    };

    const int ntiles = qt + 1;

    LOADQ(); LOADK(0); LOADV(0); CP_COMMIT();
    if (ntiles > 1) LOADV(1);
    CP_COMMIT();

    float m0 = -1e30f, m1 = -1e30f, l0 = 0.f, l1 = 0.f;
    float oacc[16][4];
#pragma unroll
    for (int i = 0; i < 16; i++)
#pragma unroll
        for (int j = 0; j < 4; j++) oacc[i][j] = 0.f;

    for (int st = 0; st < ntiles; st++) {
        const int s0 = st * 128;

        CP_WAIT(1);
        __syncthreads();

        float sacc[16][4];
#pragma unroll
        for (int i = 0; i < 16; i++)
#pragma unroll
            for (int j = 0; j < 4; j++) sacc[i][j] = 0.f;

        const uint32_t* qrow = Qs + (wm + gID) * QSTR;
#pragma unroll
        for (int kk = 0; kk < 8; kk++) {
            const int k0 = kk * 8;
            uint32_t a0 = qrow[k0 + tig];
            uint32_t a1 = qrow[8 * QSTR + k0 + tig];
            uint32_t a2 = qrow[k0 + tig + 4];
            uint32_t a3 = qrow[8 * QSTR + k0 + tig + 4];
#pragma unroll
            for (int ni = 0; ni < 16; ni++) {
                const uint32_t* kp = Ks + (gID + ni * 8) * KSTR + k0;
                MMA_F16(sacc[ni], a0, a1, a2, a3, kp[tig], kp[tig + 4]);
            }
        }
        __syncthreads();

        if (st + 1 < ntiles) LOADK(st + 1);
        CP_COMMIT();

        const int lim0 = row0 - s0;
        const int lim1 = lim0 + 8;
        const bool diag = (st == qt);
        float mx0 = -1e30f, mx1 = -1e30f;
#pragma unroll
        for (int ni = 0; ni < 16; ni++) {
#pragma unroll
            for (int c = 0; c < 2; c++) {
                int j = ni * 8 + tig * 2 + c;
                float v0 = sacc[ni][c];
                float v1 = sacc[ni][2 + c];
                if (diag) {
                    if (j > lim0) v0 = -1e30f;
                    if (j > lim1) v1 = -1e30f;
                }
                sacc[ni][c]     = v0;
                sacc[ni][2 + c] = v1;
                mx0 = fmaxf(mx0, v0);
                mx1 = fmaxf(mx1, v1);
            }
        }
        mx0 = fmaxf(mx0, __shfl_xor_sync(0xffffffffu, mx0, 1));
        mx0 = fmaxf(mx0, __shfl_xor_sync(0xffffffffu, mx0, 2));
        mx1 = fmaxf(mx1, __shfl_xor_sync(0xffffffffu, mx1, 1));
        mx1 = fmaxf(mx1, __shfl_xor_sync(0xffffffffu, mx1, 2));
        float mn0 = fmaxf(m0, mx0), mn1 = fmaxf(m1, mx1);
        float cr0 = __expf(m0 - mn0), cr1 = __expf(m1 - mn1);
        float sum0 = 0.f, sum1 = 0.f;
#pragma unroll
        for (int ni = 0; ni < 16; ni++) {
#pragma unroll
            for (int c = 0; c < 2; c++) {
                float p0 = __expf(sacc[ni][c] - mn0);
                float p1 = __expf(sacc[ni][2 + c] - mn1);
                sacc[ni][c]     = p0;
                sacc[ni][2 + c] = p1;
                sum0 += p0;
                sum1 += p1;
            }
        }
        sum0 += __shfl_xor_sync(0xffffffffu, sum0, 1);
        sum0 += __shfl_xor_sync(0xffffffffu, sum0, 2);
        sum1 += __shfl_xor_sync(0xffffffffu, sum1, 1);
        sum1 += __shfl_xor_sync(0xffffffffu, sum1, 2);
        l0 = l0 * cr0 + sum0;
        l1 = l1 * cr1 + sum1;
        m0 = mn0; m1 = mn1;

#pragma unroll
        for (int ni = 0; ni < 16; ni++) {
            oacc[ni][0] *= cr0; oacc[ni][1] *= cr0;
            oacc[ni][2] *= cr1; oacc[ni][3] *= cr1;
        }

        uint32_t* pr0 = Ps + (wm + gID) * PSTR;
        uint32_t* pr1 = pr0 + 8 * PSTR;
#pragma unroll
        for (int ni = 0; ni < 16; ni++) {
            pr0[ni * 4 + tig] = h2bits(sacc[ni][0], sacc[ni][1]);
            pr1[ni * 4 + tig] = h2bits(sacc[ni][2], sacc[ni][3]);
        }
        __syncwarp();

        const uint32_t* vbuf = Vsb + (st & 1) * 128 * VSTR;
        const uint32_t* prow = Ps + (wm + gID) * PSTR;
#pragma unroll
        for (int kk = 0; kk < 8; kk++) {
            const int k0 = kk * 8;
            uint32_t a0 = prow[k0 + tig];
            uint32_t a1 = prow[8 * PSTR + k0 + tig];
            uint32_t a2 = prow[k0 + tig + 4];
            uint32_t a3 = prow[8 * PSTR + k0 + tig + 4];
#pragma unroll
            for (int ni = 0; ni < 16; ni++) {
                const uint32_t* vp = vbuf + (gID + ni * 8) * VSTR + k0;
                MMA_F16(oacc[ni], a0, a1, a2, a3, vp[tig], vp[tig + 4]);
            }
        }
        __syncthreads();

        if (st + 2 < ntiles) LOADV(st + 2);
        CP_COMMIT();
    }

    float li0 = 1.f / l0, li1 = 1.f / l1;
    __half* y0 = Y + (size_t)(b * TT + row0) * DD + hh * HD;
    __half* y1 = y0 + (size_t)8 * DD;
#pragma unroll
    for (int ni = 0; ni < 16; ni++) {
        int c = ni * 8 + tig * 2;
        *(__half2*)(y0 + c) = __floats2half2_rn(oacc[ni][0] * li0,
                                                oacc[ni][1] * li0);
        *(__half2*)(y1 + c) = __floats2half2_rn(oacc[ni][2] * li1,
                                                oacc[ni][3] * li1);
    }
}

// ---------------------------------------------------------------------------
extern "C" void kernel_launch(void* const* d_in, const int* in_sizes, int n_in,
                              void* d_out, int out_size)
{
    const float* x  = (const float*)d_in[0];
    const float* Wq = (const float*)d_in[1];
    const float* Wk = (const float*)d_in[2];
    const float* Wv = (const float*)d_in[3];
    const float* Wo = (const float*)d_in[4];
    float* out = (float*)d_out;

    __half *xh, *Wqkvh, *Woh, *Qh, *Kh, *Vt, *Yh;
    cudaGetSymbolAddress((void**)&xh,    g_xh);
    cudaGetSymbolAddress((void**)&Wqkvh, g_Wqkvh);
    cudaGetSymbolAddress((void**)&Woh,   g_Woh);
    cudaGetSymbolAddress((void**)&Qh,    g_Qh);
    cudaGetSymbolAddress((void**)&Kh,    g_Kh);
    cudaGetSymbolAddress((void**)&Vt,    g_Vt);
    cudaGetSymbolAddress((void**)&Yh,    g_Yh);

    static bool attr_set = false;
    if (!attr_set) {
        cudaFuncSetAttribute(gemm_qkv_h,
                             cudaFuncAttributeMaxDynamicSharedMemorySize,
                             GEMM_SMEM);
        cudaFuncSetAttribute(gemm_wo_h,
                             cudaFuncAttributeMaxDynamicSharedMemorySize,
                             GEMM_SMEM);
        cudaFuncSetAttribute(attn_h,
                             cudaFuncAttributeMaxDynamicSharedMemorySize,
                             ATTN_SMEM);
        attr_set = true;
    }

    rope_table_kernel<<<TT, 64>>>();
    cvt_h<<<(MROWS * DD) / 1024, 256>>>(x, xh);
    tr_cvt_all<<<dim3(64, 64, 4), dim3(32, 8)>>>(Wq, Wk, Wv, Wo, Wqkvh, Woh);

    // Fused QKV projection + RoPE (+Q scaling) -> half Qh/Kh, transposed Vt
    gemm_qkv_h<<<dim3(NQKV / 128, MROWS / 128), 128, GEMM_SMEM>>>(
        xh, Wqkvh, Qh, Kh, Vt);

    // FP16 flash attention (BQ=BS=128) -> Yh
    attn_h<<<dim3(TT / 128, NH, BB), 256, ATTN_SMEM>>>(Qh, Kh, Vt, Yh);

    // Output projection
    gemm_wo_h<<<dim3(DD / 128, MROWS / 128), 128, GEMM_SMEM>>>(Yh, Woh, out);
}

// round 17
// speedup vs baseline: 1.1095x; 1.0132x over previous
#include <cuda_runtime.h>
#include <cuda_fp16.h>
#include <math.h>
#include <stdint.h>

#define BB 4
#define TT 1024
#define DD 2048
#define NH 16
#define NKV 4
#define HD 128
#define MROWS (BB*TT)    // 4096
#define NQKV 3072
#define SCALE 0.08838834764831845f   // 1/sqrt(128)

// Scratch (device globals; no runtime allocation)
__device__ __half   g_xh[MROWS * DD];          // x fp16 [4096][2048]
__device__ __half   g_Wqkvh[NQKV * DD];        // [Wq|Wk|Wv]^T fp16 [3072][2048]
__device__ __half   g_Woh[DD * DD];            // Wo^T fp16
__device__ __half   g_Qh[BB * NH * TT * HD];   // roped+scaled Q half [b][h][t][d]
__device__ __half   g_Kh[BB * NKV * TT * HD];  // roped K half [b][g][t][d]
__device__ __half   g_Vt[BB * NKV * HD * TT];  // V half TRANSPOSED [b][g][d][t]
__device__ __half   g_Yh[MROWS * DD];          // attention out half
__device__ float    g_cos[TT * 64];
__device__ float    g_sin[TT * 64];

#define MMA_F16(ACC, A0, A1, A2, A3, B0, B1)                                   \
    asm volatile(                                                              \
        "mma.sync.aligned.m16n8k16.row.col.f32.f16.f16.f32 "                   \
        "{%0,%1,%2,%3}, {%4,%5,%6,%7}, {%8,%9}, {%0,%1,%2,%3};"                \
        : "+f"((ACC)[0]), "+f"((ACC)[1]), "+f"((ACC)[2]), "+f"((ACC)[3])       \
        : "r"(A0), "r"(A1), "r"(A2), "r"(A3), "r"(B0), "r"(B1))

#define LDSM_X4(R, ADDR)                                                       \
    asm volatile(                                                              \
        "ldmatrix.sync.aligned.m8n8.x4.shared.b16 {%0,%1,%2,%3}, [%4];"        \
        : "=r"((R)[0]), "=r"((R)[1]), "=r"((R)[2]), "=r"((R)[3])               \
        : "r"(ADDR))

__device__ __forceinline__ void cp16(uint32_t dst, const void* src) {
    asm volatile("cp.async.cg.shared.global [%0], [%1], 16;" ::
                 "r"(dst), "l"(src));
}
#define CP_COMMIT() asm volatile("cp.async.commit_group;")
#define CP_WAIT(n)  asm volatile("cp.async.wait_group %0;" :: "n"(n) : "memory")

__device__ __forceinline__ uint32_t h2bits(float a, float b) {
    __half2 h = __floats2half2_rn(a, b);
    return *(uint32_t*)&h;
}

// ---------------------------------------------------------------------------
// FP16 GEMM (unchanged from R16 best): CTA 128x128, 128 thr, warp 64x64,
// KT=32, 4 stages, LDSM fragment loads, 2 CTAs/SM.
// ---------------------------------------------------------------------------
#define HSTR 20                   // u32 per row
#define HAW  (128*HSTR)
#define HSTG (2*HAW)
#define GEMM_SMEM (4*HSTG*4)      // 81920 B

#define GEMM_MAINLOOP_H(Aptr, Bptr)                                            \
    auto LOAD = [&](int kt, int s) {                                           \
        uint32_t abase = smaddr + (uint32_t)(s * HSTG) * 4;                    \
        _Pragma("unroll")                                                      \
        for (int p = 0; p < 4; p++) {                                          \
            int id = tid + p * 128;                                            \
            int row = id >> 2, ch = id & 3;                                    \
            cp16(abase + (uint32_t)(row * 80 + ch * 16),                       \
                 (Aptr) + (size_t)(bm + row) * DD + kt * 32 + ch * 8);         \
        }                                                                      \
        uint32_t bbase = abase + HAW * 4;                                      \
        _Pragma("unroll")                                                      \
        for (int p = 0; p < 4; p++) {                                          \
            int id = tid + p * 128;                                            \
            int row = id >> 2, ch = id & 3;                                    \
            cp16(bbase + (uint32_t)(row * 80 + ch * 16),                       \
                 (Bptr) + (size_t)(bn + row) * DD + kt * 32 + ch * 8);         \
        }                                                                      \
        CP_COMMIT();                                                           \
    };                                                                         \
    LOAD(0, 0); LOAD(1, 1); LOAD(2, 2);                                        \
    for (int kt = 0; kt < 64; kt++) {                                          \
        CP_WAIT(2);                                                            \
        __syncthreads();                                                       \
        if (kt + 3 < 64) LOAD(kt + 3, (kt + 3) & 3);                           \
        else CP_COMMIT();                                                      \
        const uint32_t sbase = smaddr + (uint32_t)((kt & 3) * HSTG) * 4;       \
        const uint32_t aaddr = sbase + a_off;                                  \
        const uint32_t baddr = sbase + HAW * 4 + b_off;                        \
        uint32_t af[2][4][4], bf[2][4][4];                                     \
        _Pragma("unroll")                                                      \
        for (int kk = 0; kk < 2; kk++) {                                       \
            _Pragma("unroll")                                                  \
            for (int mi = 0; mi < 4; mi++)                                     \
                LDSM_X4(af[kk][mi], aaddr + mi * 1280 + kk * 32);              \
            _Pragma("unroll")                                                  \
            for (int np = 0; np < 4; np++)                                     \
                LDSM_X4(bf[kk][np], baddr + np * 1280 + kk * 32);              \
        }                                                                      \
        _Pragma("unroll")                                                      \
        for (int kk = 0; kk < 2; kk++)                                         \
            _Pragma("unroll")                                                  \
            for (int mi = 0; mi < 4; mi++)                                     \
                _Pragma("unroll")                                              \
                for (int ni = 0; ni < 8; ni++)                                 \
                    MMA_F16(acc[mi][ni], af[kk][mi][0], af[kk][mi][1],         \
                            af[kk][mi][2], af[kk][mi][3],                      \
                            bf[kk][ni >> 1][(ni & 1) * 2],                     \
                            bf[kk][ni >> 1][(ni & 1) * 2 + 1]);                \
    }

#define GEMM_LDSM_OFFS()                                                       \
    const uint32_t a_off = (uint32_t)((wm + (lane & 7) + ((lane >> 3) & 1) * 8)\
                                       * 80 + ((lane >> 4) & 1) * 16);         \
    const uint32_t b_off = (uint32_t)((wn + (lane & 7) + ((lane >> 4) & 1) * 8)\
                                       * 80 + ((lane >> 3) & 1) * 16)

// ---------------------------------------------------------------------------
// Fused QKV projection (fp16) + RoPE epilogue. Q is pre-scaled by 1/sqrt(d).
// ---------------------------------------------------------------------------
__global__ __launch_bounds__(128, 2) void gemm_qkv_h(
    const __half* __restrict__ A, const __half* __restrict__ B,
    __half* __restrict__ Qh, __half* __restrict__ Kh,
    __half* __restrict__ Vt)
{
    extern __shared__ uint32_t smg[];
    const uint32_t smaddr = (uint32_t)__cvta_generic_to_shared(smg);

    const int tid  = threadIdx.x;
    const int bm   = blockIdx.y * 128;
    const int bn   = blockIdx.x * 128;
    const int warp = tid >> 5, lane = tid & 31;
    const int wm   = (warp & 1) * 64;
    const int wn   = (warp >> 1) * 64;
    const int gID  = lane >> 2, tig = lane & 3;
    GEMM_LDSM_OFFS();

    float acc[4][8][4];
#pragma unroll
    for (int i = 0; i < 4; i++)
#pragma unroll
        for (int j = 0; j < 8; j++)
#pragma unroll
            for (int l = 0; l < 4; l++) acc[i][j][l] = 0.f;

    GEMM_MAINLOOP_H(A, B)

    __syncthreads();
    float* Cs = (float*)smg;
#pragma unroll
    for (int mi = 0; mi < 4; mi++) {
        const int r0 = wm + mi * 16 + gID;
#pragma unroll
        for (int ni = 0; ni < 8; ni++) {
            const int c = wn + ni * 8 + tig * 2;
            Cs[r0 * 132 + c]     = acc[mi][ni][0];
            Cs[r0 * 132 + c + 1] = acc[mi][ni][1];
            Cs[(r0 + 8) * 132 + c]     = acc[mi][ni][2];
            Cs[(r0 + 8) * 132 + c + 1] = acc[mi][ni][3];
        }
    }
    __syncthreads();

    const int bb = bm >> 10;
    if (bn < 2560) {
        __half* dst;
        int head, hs;
        float sc;
        if (bn < 2048) { dst = Qh; head = bn >> 7;          hs = NH;  sc = SCALE; }
        else           { dst = Kh; head = (bn - 2048) >> 7; hs = NKV; sc = 1.f;   }
#pragma unroll 4
        for (int p = 0; p < 32; p++) {
            int idx = tid + p * 128;
            int r = idx >> 5;
            int d2 = (idx & 31) << 1;
            int t = (bm + r) & (TT - 1);
            float lo0 = Cs[r * 132 + d2] * sc;
            float lo1 = Cs[r * 132 + d2 + 1] * sc;
            float hi0 = Cs[r * 132 + d2 + 64] * sc;
            float hi1 = Cs[r * 132 + d2 + 65] * sc;
            float2 cc = *(const float2*)(g_cos + t * 64 + d2);
            float2 ss = *(const float2*)(g_sin + t * 64 + d2);
            __half* o = dst + ((size_t)(bb * hs + head) * TT + t) * HD;
            *(__half2*)(o + d2) =
                __floats2half2_rn(lo0 * cc.x - hi0 * ss.x,
                                  lo1 * cc.y - hi1 * ss.y);
            *(__half2*)(o + d2 + 64) =
                __floats2half2_rn(hi0 * cc.x + lo0 * ss.x,
                                  hi1 * cc.y + lo1 * ss.y);
        }
    } else {
        const int head = (bn - 2560) >> 7;
        const int d = tid;
        const int t0 = bm & (TT - 1);
        __half* o = Vt + ((size_t)(bb * NKV + head) * HD + d) * TT + t0;
#pragma unroll 8
        for (int tq = 0; tq < 128; tq += 2) {
            float v0 = Cs[tq * 132 + d];
            float v1 = Cs[(tq + 1) * 132 + d];
            *(__half2*)(o + tq) = __floats2half2_rn(v0, v1);
        }
    }
}

// ---------------------------------------------------------------------------
// Wo projection (fp16): out fp32 = Yh @ Woh^T-tile
// ---------------------------------------------------------------------------
__global__ __launch_bounds__(128, 2) void gemm_wo_h(
    const __half* __restrict__ A, const __half* __restrict__ B,
    float* __restrict__ C)
{
    extern __shared__ uint32_t smg[];
    const uint32_t smaddr = (uint32_t)__cvta_generic_to_shared(smg);

    const int tid  = threadIdx.x;
    const int bm   = blockIdx.y * 128;
    const int bn   = blockIdx.x * 128;
    const int warp = tid >> 5, lane = tid & 31;
    const int wm   = (warp & 1) * 64;
    const int wn   = (warp >> 1) * 64;
    const int gID  = lane >> 2, tig = lane & 3;
    GEMM_LDSM_OFFS();

    float acc[4][8][4];
#pragma unroll
    for (int i = 0; i < 4; i++)
#pragma unroll
        for (int j = 0; j < 8; j++)
#pragma unroll
            for (int l = 0; l < 4; l++) acc[i][j][l] = 0.f;

    GEMM_MAINLOOP_H(A, B)

#pragma unroll
    for (int mi = 0; mi < 4; mi++) {
        const int r0 = bm + wm + mi * 16 + gID;
#pragma unroll
        for (int ni = 0; ni < 8; ni++) {
            const int c = bn + wn + ni * 8 + tig * 2;
            *(float2*)&C[(size_t)r0 * DD + c] =
                make_float2(acc[mi][ni][0], acc[mi][ni][1]);
            *(float2*)&C[(size_t)(r0 + 8) * DD + c] =
                make_float2(acc[mi][ni][2], acc[mi][ni][3]);
        }
    }
}

// ---------------------------------------------------------------------------
// Prep kernels: cvt_h also builds the rope table (blocks >= 8192).
// ---------------------------------------------------------------------------
__global__ void cvt_h(const float* __restrict__ in, __half* __restrict__ out)
{
    if (blockIdx.x < 8192) {
        int i = (blockIdx.x * 256 + threadIdx.x) * 4;
        float4 v = *(const float4*)(in + i);
        *(__half2*)(out + i)     = __floats2half2_rn(v.x, v.y);
        *(__half2*)(out + i + 2) = __floats2half2_rn(v.z, v.w);
    } else {
        int idx = (blockIdx.x - 8192) * 256 + threadIdx.x;   // 0..65535
        int t = idx >> 6, i = idx & 63;
        float inv = powf(10000.0f, -(float)i / 64.0f);
        float ang = (float)t * inv;
        g_cos[idx] = cosf(ang);
        g_sin[idx] = sinf(ang);
    }
}

__global__ void tr_cvt_all(const float* __restrict__ Wq,
                           const float* __restrict__ Wk,
                           const float* __restrict__ Wv,
                           const float* __restrict__ Wo,
                           __half* __restrict__ Wqkvh,
                           __half* __restrict__ Woh)
{
    __shared__ float tile[32][33];
    const int z = blockIdx.z;
    const float* src;
    __half* dst;
    int C, row_off;
    if      (z == 0) { src = Wq; dst = Wqkvh; C = 2048; row_off = 0;    }
    else if (z == 1) { src = Wk; dst = Wqkvh; C = 512;  row_off = 2048; }
    else if (z == 2) { src = Wv; dst = Wqkvh; C = 512;  row_off = 2560; }
    else             { src = Wo; dst = Woh;   C = 2048; row_off = 0;    }

    int bx = blockIdx.x * 32;
    if (bx >= C) return;
    int by = blockIdx.y * 32;
    int x = threadIdx.x, y = threadIdx.y;
#pragma unroll
    for (int j = 0; j < 32; j += 8)
        tile[y + j][x] = src[(size_t)(by + y + j) * C + bx + x];
    __syncthreads();
#pragma unroll
    for (int j = 0; j < 32; j += 8)
        dst[(size_t)(row_off + bx + y + j) * 2048 + by + x] =
            __float2half(tile[x][y + j]);
}

// ---------------------------------------------------------------------------
// FP16 flash attention, causal, GQA. BQ=128, BS=128. LDSM fragment loads.
// ---------------------------------------------------------------------------
#define QSTR 68
#define KSTR 68
#define VSTR 68
#define PSTR 68
#define ATTN_SMEM (43520 * 4)

__global__ __launch_bounds__(256, 1) void attn_h(
    const __half* __restrict__ Qh, const __half* __restrict__ Kh,
    const __half* __restrict__ Vt, __half* __restrict__ Y)
{
    extern __shared__ uint32_t sma[];
    uint32_t* Ps  = sma + 128 * QSTR + 128 * KSTR + 2 * 128 * VSTR;
    const uint32_t smaddr = (uint32_t)__cvta_generic_to_shared(sma);
    const uint32_t Qs_a = smaddr;
    const uint32_t Ks_a = Qs_a + 128 * QSTR * 4;
    const uint32_t Vs_a = Ks_a + 128 * KSTR * 4;
    const uint32_t Ps_a = Vs_a + 2 * 128 * VSTR * 4;

    const int tid  = threadIdx.x;
    const int warp = tid >> 5, lane = tid & 31;
    const int gID  = lane >> 2, tig = lane & 3;
    const int qt   = (gridDim.x - 1) - blockIdx.x;
    const int hh   = blockIdx.y;
    const int b    = blockIdx.z;
    const int gkv  = hh >> 2;
    const int q0   = qt * 128;
    const int wm   = warp * 16;
    const int row0 = q0 + wm + gID;

    // LDSM lane offsets (strides 272 B; rows*272 mod 128 distinct -> no conflicts)
    const uint32_t lrow8 = (lane & 7) + ((lane >> 3) & 1) * 8;   // A pattern row
    const uint32_t brow8 = (lane & 7) + ((lane >> 4) & 1) * 8;   // B pattern row
    const uint32_t qa_off = (uint32_t)((wm + lrow8) * (QSTR * 4) + ((lane >> 4) & 1) * 16);
    const uint32_t pa_off = (uint32_t)((wm + lrow8) * (PSTR * 4) + ((lane >> 4) & 1) * 16);
    const uint32_t kb_off = (uint32_t)(brow8 * (KSTR * 4) + ((lane >> 3) & 1) * 16);
    const uint32_t vb_off = (uint32_t)(brow8 * (VSTR * 4) + ((lane >> 3) & 1) * 16);

    const __half* Qbase = Qh + ((size_t)(b * NH + hh) * TT + q0) * HD;
    const __half* Kbase = Kh + (size_t)(b * NKV + gkv) * TT * HD;
    const __half* Vbase = Vt + (size_t)(b * NKV + gkv) * HD * TT;

    auto LOADQ = [&]() {
#pragma unroll
        for (int p = 0; p < 8; p++) {
            int id = tid + p * 256;
            int q = id >> 4, ch = id & 15;
            cp16(Qs_a + (uint32_t)(q * QSTR + ch * 4) * 4,
                 Qbase + q * HD + ch * 8);
        }
    };
    auto LOADK = [&](int st) {
        const __half* src = Kbase + (size_t)st * 128 * HD;
#pragma unroll
        for (int p = 0; p < 8; p++) {
            int id = tid + p * 256;
            int s = id >> 4, ch = id & 15;
            cp16(Ks_a + (uint32_t)(s * KSTR + ch * 4) * 4,
                 src + s * HD + ch * 8);
        }
    };
    auto LOADV = [&](int st) {
        const __half* src = Vbase + st * 128;
        uint32_t dbase = Vs_a + (uint32_t)((st & 1) * 128 * VSTR) * 4;
#pragma unroll
        for (int p = 0; p < 8; p++) {
            int id = tid + p * 256;
            int d = id >> 4, ch = id & 15;
            cp16(dbase + (uint32_t)(d * VSTR + ch * 4) * 4,
                 src + (size_t)d * TT + ch * 8);
        }
    };

    const int ntiles = qt + 1;

    LOADQ(); LOADK(0); LOADV(0); CP_COMMIT();
    if (ntiles > 1) LOADV(1);
    CP_COMMIT();

    float m0 = -1e30f, m1 = -1e30f, l0 = 0.f, l1 = 0.f;
    float oacc[16][4];
#pragma unroll
    for (int i = 0; i < 16; i++)
#pragma unroll
        for (int j = 0; j < 4; j++) oacc[i][j] = 0.f;

    for (int st = 0; st < ntiles; st++) {
        const int s0 = st * 128;

        CP_WAIT(1);
        __syncthreads();

        // ---- S = Q @ K^T (LDSM fragments) ----
        float sacc[16][4];
#pragma unroll
        for (int i = 0; i < 16; i++)
#pragma unroll
            for (int j = 0; j < 4; j++) sacc[i][j] = 0.f;

#pragma unroll
        for (int kk = 0; kk < 8; kk++) {
            uint32_t aq[4], bk[8][4];
            LDSM_X4(aq, Qs_a + qa_off + kk * 32);
#pragma unroll
            for (int np = 0; np < 8; np++)
                LDSM_X4(bk[np], Ks_a + kb_off + np * (16 * KSTR * 4) + kk * 32);
#pragma unroll
            for (int ni = 0; ni < 16; ni++)
                MMA_F16(sacc[ni], aq[0], aq[1], aq[2], aq[3],
                        bk[ni >> 1][(ni & 1) * 2], bk[ni >> 1][(ni & 1) * 2 + 1]);
        }
        __syncthreads();

        if (st + 1 < ntiles) LOADK(st + 1);
        CP_COMMIT();

        // ---- softmax ----
        const int lim0 = row0 - s0;
        const int lim1 = lim0 + 8;
        const bool diag = (st == qt);
        float mx0 = -1e30f, mx1 = -1e30f;
#pragma unroll
        for (int ni = 0; ni < 16; ni++) {
#pragma unroll
            for (int c = 0; c < 2; c++) {
                int j = ni * 8 + tig * 2 + c;
                float v0 = sacc[ni][c];
                float v1 = sacc[ni][2 + c];
                if (diag) {
                    if (j > lim0) v0 = -1e30f;
                    if (j > lim1) v1 = -1e30f;
                }
                sacc[ni][c]     = v0;
                sacc[ni][2 + c] = v1;
                mx0 = fmaxf(mx0, v0);
                mx1 = fmaxf(mx1, v1);
            }
        }
        mx0 = fmaxf(mx0, __shfl_xor_sync(0xffffffffu, mx0, 1));
        mx0 = fmaxf(mx0, __shfl_xor_sync(0xffffffffu, mx0, 2));
        mx1 = fmaxf(mx1, __shfl_xor_sync(0xffffffffu, mx1, 1));
        mx1 = fmaxf(mx1, __shfl_xor_sync(0xffffffffu, mx1, 2));
        float mn0 = fmaxf(m0, mx0), mn1 = fmaxf(m1, mx1);
        float cr0 = __expf(m0 - mn0), cr1 = __expf(m1 - mn1);
        float sum0 = 0.f, sum1 = 0.f;
#pragma unroll
        for (int ni = 0; ni < 16; ni++) {
#pragma unroll
            for (int c = 0; c < 2; c++) {
                float p0 = __expf(sacc[ni][c] - mn0);
                float p1 = __expf(sacc[ni][2 + c] - mn1);
                sacc[ni][c]     = p0;
                sacc[ni][2 + c] = p1;
                sum0 += p0;
                sum1 += p1;
            }
        }
        sum0 += __shfl_xor_sync(0xffffffffu, sum0, 1);
        sum0 += __shfl_xor_sync(0xffffffffu, sum0, 2);
        sum1 += __shfl_xor_sync(0xffffffffu, sum1, 1);
        sum1 += __shfl_xor_sync(0xffffffffu, sum1, 2);
        l0 = l0 * cr0 + sum0;
        l1 = l1 * cr1 + sum1;
        m0 = mn0; m1 = mn1;

#pragma unroll
        for (int ni = 0; ni < 16; ni++) {
            oacc[ni][0] *= cr0; oacc[ni][1] *= cr0;
            oacc[ni][2] *= cr1; oacc[ni][3] *= cr1;
        }

        // ---- write P (half2 packs), re-read by same warp via LDSM ----
        uint32_t* pr0 = Ps + (wm + gID) * PSTR;
        uint32_t* pr1 = pr0 + 8 * PSTR;
#pragma unroll
        for (int ni = 0; ni < 16; ni++) {
            pr0[ni * 4 + tig] = h2bits(sacc[ni][0], sacc[ni][1]);
            pr1[ni * 4 + tig] = h2bits(sacc[ni][2], sacc[ni][3]);
        }
        __syncwarp();

        // ---- O += P @ V (LDSM fragments) ----
        const uint32_t vb_base = Vs_a + (uint32_t)((st & 1) * 128 * VSTR) * 4 + vb_off;
#pragma unroll
        for (int kk = 0; kk < 8; kk++) {
            uint32_t ap[4], bv[8][4];
            LDSM_X4(ap, Ps_a + pa_off + kk * 32);
#pragma unroll
            for (int np = 0; np < 8; np++)
                LDSM_X4(bv[np], vb_base + np * (16 * VSTR * 4) + kk * 32);
#pragma unroll
            for (int ni = 0; ni < 16; ni++)
                MMA_F16(oacc[ni], ap[0], ap[1], ap[2], ap[3],
                        bv[ni >> 1][(ni & 1) * 2], bv[ni >> 1][(ni & 1) * 2 + 1]);
        }
        __syncthreads();

        if (st + 2 < ntiles) LOADV(st + 2);
        CP_COMMIT();
    }

    float li0 = 1.f / l0, li1 = 1.f / l1;
    __half* y0 = Y + (size_t)(b * TT + row0) * DD + hh * HD;
    __half* y1 = y0 + (size_t)8 * DD;
#pragma unroll
    for (int ni = 0; ni < 16; ni++) {
        int c = ni * 8 + tig * 2;
        *(__half2*)(y0 + c) = __floats2half2_rn(oacc[ni][0] * li0,
                                                oacc[ni][1] * li0);
        *(__half2*)(y1 + c) = __floats2half2_rn(oacc[ni][2] * li1,
                                                oacc[ni][3] * li1);
    }
}

// ---------------------------------------------------------------------------
extern "C" void kernel_launch(void* const* d_in, const int* in_sizes, int n_in,
                              void* d_out, int out_size)
{
    const float* x  = (const float*)d_in[0];
    const float* Wq = (const float*)d_in[1];
    const float* Wk = (const float*)d_in[2];
    const float* Wv = (const float*)d_in[3];
    const float* Wo = (const float*)d_in[4];
    float* out = (float*)d_out;

    __half *xh, *Wqkvh, *Woh, *Qh, *Kh, *Vt, *Yh;
    cudaGetSymbolAddress((void**)&xh,    g_xh);
    cudaGetSymbolAddress((void**)&Wqkvh, g_Wqkvh);
    cudaGetSymbolAddress((void**)&Woh,   g_Woh);
    cudaGetSymbolAddress((void**)&Qh,    g_Qh);
    cudaGetSymbolAddress((void**)&Kh,    g_Kh);
    cudaGetSymbolAddress((void**)&Vt,    g_Vt);
    cudaGetSymbolAddress((void**)&Yh,    g_Yh);

    static bool attr_set = false;
    if (!attr_set) {
        cudaFuncSetAttribute(gemm_qkv_h,
                             cudaFuncAttributeMaxDynamicSharedMemorySize,
                             GEMM_SMEM);
        cudaFuncSetAttribute(gemm_wo_h,
                             cudaFuncAttributeMaxDynamicSharedMemorySize,
                             GEMM_SMEM);
        cudaFuncSetAttribute(attn_h,
                             cudaFuncAttributeMaxDynamicSharedMemorySize,
                             ATTN_SMEM);
        attr_set = true;
    }

    cvt_h<<<8192 + 256, 256>>>(x, xh);   // x->fp16 + rope table
    tr_cvt_all<<<dim3(64, 64, 4), dim3(32, 8)>>>(Wq, Wk, Wv, Wo, Wqkvh, Woh);

    // Fused QKV projection + RoPE (+Q scaling) -> half Qh/Kh, transposed Vt
    gemm_qkv_h<<<dim3(NQKV / 128, MROWS / 128), 128, GEMM_SMEM>>>(
        xh, Wqkvh, Qh, Kh, Vt);

    // FP16 flash attention (BQ=BS=128, LDSM) -> Yh
    attn_h<<<dim3(TT / 128, NH, BB), 256, ATTN_SMEM>>>(Qh, Kh, Vt, Yh);

    // Output projection
    gemm_wo_h<<<dim3(DD / 128, MROWS / 128), 128, GEMM_SMEM>>>(Yh, Woh, out);
}